// round 4
// baseline (speedup 1.0000x reference)
#include <cuda_runtime.h>

#define TT 512
#define BB 16384
#define HH 32
#define RL 4              // batch lanes per thread
#define BLK 128
#define LPC 64            // lanes per CTA
#define AST 36            // floats per act row (16B-aligned, conflict-free w/ row perm)

typedef unsigned long long u64;

// ---- packed f32x2 helpers (PTX-only; ptxas never auto-fuses) ----
__device__ __forceinline__ u64 fma2(u64 a, u64 b, u64 c) {
    u64 d; asm("fma.rn.f32x2 %0,%1,%2,%3;" : "=l"(d) : "l"(a), "l"(b), "l"(c)); return d;
}
__device__ __forceinline__ u64 mul2(u64 a, u64 b) {
    u64 d; asm("mul.rn.f32x2 %0,%1,%2;" : "=l"(d) : "l"(a), "l"(b)); return d;
}
__device__ __forceinline__ u64 pack2(float lo, float hi) {
    u64 r; asm("mov.b64 %0,{%1,%2};" : "=l"(r) : "f"(lo), "f"(hi)); return r;
}
__device__ __forceinline__ u64 dup2(float x) { return pack2(x, x); }
__device__ __forceinline__ void unpack2(u64 v, float& lo, float& hi) {
    asm("mov.b64 {%0,%1},%2;" : "=f"(lo), "=f"(hi) : "l"(v));
}

// stable softplus + sigmoid sharing one exp
__device__ __forceinline__ void sp_sig(float z, float& sp, float& sg) {
    float u = __expf(-fabsf(z));
    float d = 1.0f + u;
    float r = __fdividef(1.0f, d);
    sp = fmaxf(z, 0.0f) + __logf(d);
    sg = (z >= 0.0f) ? r : 1.0f - r;
}
__device__ __forceinline__ float sigf(float z) {
    float u = __expf(-fabsf(z));
    float r = __fdividef(1.0f, 1.0f + u);
    return (z >= 0.0f) ? r : 1.0f - r;
}

__global__ void __launch_bounds__(BLK, 2) rnncell_o8r4_kernel(
    const float* __restrict__ eps, const float* __restrict__ hs,
    const float* __restrict__ W1,  const float* __restrict__ b1,
    const float* __restrict__ W2,  const float* __restrict__ b2,
    const float* __restrict__ W3,  float* __restrict__ out)
{
    __shared__ __align__(16) float sW2 [HH * HH];     // W2[k][j]
    __shared__ __align__(16) float sW2T[HH * HH];     // W2T[j][k]
    __shared__ __align__(16) float sAct[LPC * AST];   // staged activations

    const int tid = threadIdx.x;
    for (int i = tid; i < HH * HH; i += BLK) {
        float w = W2[i];
        sW2[i] = w;
        sW2T[(i & 31) * HH + (i >> 5)] = w;
    }
    __syncthreads();

    const int oct = tid & 7;          // unit-chunk: 4 units at co
    const int grp = tid >> 3;         // group 0..15 within CTA
    const int co  = oct * 4;

    // lanes: 4 consecutive gids -> vector LDG/STG
    const int gbase = blockIdx.x * LPC + grp * RL;

    // staging row for lane (grp,r) = r*16 + grp  (warp-instr touches 4
    // consecutive rows -> bank offsets {0,16,32,48} mod 128, conflict-free)
    float* act[RL];
    #pragma unroll
    for (int r = 0; r < RL; ++r) act[r] = sAct + (r * 16 + grp) * AST;

    // loop-invariant per-chunk weights in registers
    u64 w1ap[2], w1bp[2], b1p[2], b2p[2];
    float w3s[4];
    #pragma unroll
    for (int j = 0; j < 2; ++j) {
        w1ap[j] = pack2(W1[co + 2*j],      W1[co + 2*j + 1]);
        w1bp[j] = pack2(W1[HH + co + 2*j], W1[HH + co + 2*j + 1]);
        b1p [j] = pack2(b1[co + 2*j],      b1[co + 2*j + 1]);
        b2p [j] = pack2(b2[co + 2*j],      b2[co + 2*j + 1]);
    }
    #pragma unroll
    for (int j = 0; j < 4; ++j) w3s[j] = W3[co + j];

    float gam[RL], ec[RL], hc[RL];
    {
        float4 e4 = *(const float4*)(eps + gbase);
        float4 h4 = *(const float4*)(hs  + gbase);
        ec[0]=e4.x; ec[1]=e4.y; ec[2]=e4.z; ec[3]=e4.w;
        hc[0]=h4.x; hc[1]=h4.y; hc[2]=h4.z; hc[3]=h4.w;
        #pragma unroll
        for (int r = 0; r < RL; ++r) gam[r] = 0.0f;
    }

    for (int t = 0; t < TT; ++t) {
        // prefetch next step inputs (vector)
        const int tn = (t + 1 < TT) ? t + 1 : t;
        float4 en4 = *(const float4*)(eps + (size_t)tn * BB + gbase);
        float4 hn4 = *(const float4*)(hs  + (size_t)tn * BB + gbase);

        // ---- layer 1 (my 4 units x 4 lanes) ----
        u64 s1p[RL][2];
        #pragma unroll
        for (int r = 0; r < RL; ++r) {
            const u64 e2 = dup2(ec[r]);
            const u64 g2 = dup2(gam[r]);
            u64 z0 = fma2(e2, w1ap[0], fma2(g2, w1bp[0], b1p[0]));
            u64 z1 = fma2(e2, w1ap[1], fma2(g2, w1bp[1], b1p[1]));
            float za, zb, zc, zd;
            unpack2(z0, za, zb);
            unpack2(z1, zc, zd);
            float s0,s1,s2,s3, q0,q1,q2,q3;
            sp_sig(za, s0, q0);
            sp_sig(zb, s1, q1);
            sp_sig(zc, s2, q2);
            sp_sig(zd, s3, q3);
            *(float4*)(act[r] + co) = make_float4(s0, s1, s2, s3);
            s1p[r][0] = pack2(q0, q1);
            s1p[r][1] = pack2(q2, q3);
        }
        __syncwarp();

        // ---- matvec1: z2[my 4 cols] = b2 + sum_k a1[k] * W2[k][.] ----
        u64 acc[RL][2];
        #pragma unroll
        for (int r = 0; r < RL; ++r) { acc[r][0] = b2p[0]; acc[r][1] = b2p[1]; }

        #pragma unroll
        for (int q = 0; q < 4; ++q) {
            float av[RL][8];
            #pragma unroll
            for (int r = 0; r < RL; ++r) {
                float4 lo = *(const float4*)(act[r] + q * 8);
                float4 hi = *(const float4*)(act[r] + q * 8 + 4);
                av[r][0]=lo.x; av[r][1]=lo.y; av[r][2]=lo.z; av[r][3]=lo.w;
                av[r][4]=hi.x; av[r][5]=hi.y; av[r][6]=hi.z; av[r][7]=hi.w;
            }
            #pragma unroll
            for (int kk = 0; kk < 8; ++kk) {
                const ulonglong2 w = *(const ulonglong2*)(sW2 + (q*8+kk)*HH + co);
                #pragma unroll
                for (int r = 0; r < RL; ++r) {
                    u64 ak = dup2(av[r][kk]);
                    acc[r][0] = fma2(ak, w.x, acc[r][0]);
                    acc[r][1] = fma2(ak, w.y, acc[r][1]);
                }
            }
        }
        __syncwarp();

        // ---- v2 = sigmoid(z2) * W3, staged ----
        #pragma unroll
        for (int r = 0; r < RL; ++r) {
            float za, zb, zc, zd;
            unpack2(acc[r][0], za, zb);
            unpack2(acc[r][1], zc, zd);
            *(float4*)(act[r] + co) = make_float4(
                sigf(za) * w3s[0], sigf(zb) * w3s[1],
                sigf(zc) * w3s[2], sigf(zd) * w3s[3]);
        }
        __syncwarp();

        // ---- matvec2: t[my 4 rows] = sum_j v2[j] * W2T[j][.] ----
        u64 tacc[RL][2];
        #pragma unroll
        for (int r = 0; r < RL; ++r) { tacc[r][0] = 0ull; tacc[r][1] = 0ull; }

        #pragma unroll
        for (int q = 0; q < 4; ++q) {
            float vv[RL][8];
            #pragma unroll
            for (int r = 0; r < RL; ++r) {
                float4 lo = *(const float4*)(act[r] + q * 8);
                float4 hi = *(const float4*)(act[r] + q * 8 + 4);
                vv[r][0]=lo.x; vv[r][1]=lo.y; vv[r][2]=lo.z; vv[r][3]=lo.w;
                vv[r][4]=hi.x; vv[r][5]=hi.y; vv[r][6]=hi.z; vv[r][7]=hi.w;
            }
            #pragma unroll
            for (int kk = 0; kk < 8; ++kk) {
                const ulonglong2 w = *(const ulonglong2*)(sW2T + (q*8+kk)*HH + co);
                #pragma unroll
                for (int r = 0; r < RL; ++r) {
                    u64 vk = dup2(vv[r][kk]);
                    tacc[r][0] = fma2(vk, w.x, tacc[r][0]);
                    tacc[r][1] = fma2(vk, w.y, tacc[r][1]);
                }
            }
        }
        __syncwarp();   // act free for next iteration's layer-1 staging

        // ---- v1 = sig1 .* t ; partial dots ; 8-thread butterfly ----
        float g0[RL], g1[RL];
        #pragma unroll
        for (int r = 0; r < RL; ++r) {
            u64 v1a = mul2(s1p[r][0], tacc[r][0]);
            u64 v1b = mul2(s1p[r][1], tacc[r][1]);
            u64 g0p = fma2(v1b, w1ap[1], mul2(v1a, w1ap[0]));
            u64 g1p = fma2(v1b, w1bp[1], mul2(v1a, w1bp[0]));
            float a, b;
            unpack2(g0p, a, b); g0[r] = a + b;
            unpack2(g1p, a, b); g1[r] = a + b;
        }
        #pragma unroll
        for (int r = 0; r < RL; ++r) {
            g0[r] += __shfl_xor_sync(0xffffffffu, g0[r], 1);
            g0[r] += __shfl_xor_sync(0xffffffffu, g0[r], 2);
            g0[r] += __shfl_xor_sync(0xffffffffu, g0[r], 4);
            g1[r] += __shfl_xor_sync(0xffffffffu, g1[r], 1);
            g1[r] += __shfl_xor_sync(0xffffffffu, g1[r], 2);
            g1[r] += __shfl_xor_sync(0xffffffffu, g1[r], 4);
        }

        if (oct == 0)
            *(float4*)(out + (size_t)t * BB + gbase) =
                make_float4(g0[0], g0[1], g0[2], g0[3]);

        gam[0] = fmaf(hc[0], -g1[0], gam[0]);
        gam[1] = fmaf(hc[1], -g1[1], gam[1]);
        gam[2] = fmaf(hc[2], -g1[2], gam[2]);
        gam[3] = fmaf(hc[3], -g1[3], gam[3]);

        ec[0]=en4.x; ec[1]=en4.y; ec[2]=en4.z; ec[3]=en4.w;
        hc[0]=hn4.x; hc[1]=hn4.y; hc[2]=hn4.z; hc[3]=hn4.w;
    }
}

extern "C" void kernel_launch(void* const* d_in, const int* in_sizes, int n_in,
                              void* d_out, int out_size) {
    const float* eps = (const float*)d_in[0];
    const float* hs  = (const float*)d_in[1];
    const float* W1  = (const float*)d_in[2];
    const float* b1  = (const float*)d_in[3];
    const float* W2  = (const float*)d_in[4];
    const float* b2  = (const float*)d_in[5];
    const float* W3  = (const float*)d_in[6];
    float* out = (float*)d_out;

    // 16384 lanes / 64 per CTA = 256 CTAs x 128 threads (32768 threads)
    rnncell_o8r4_kernel<<<BB / LPC, BLK>>>(eps, hs, W1, b1, W2, b2, W3, out);
}

// round 5
// speedup vs baseline: 1.3959x; 1.3959x over previous
#include <cuda_runtime.h>

#define TT 512
#define BB 16384
#define HH 32
#define RL 4              // batch lanes per thread
#define BLK 128
#define LPC 128           // lanes per CTA = (BLK/4) * RL
#define AST 36            // floats per act row

typedef unsigned long long u64;

// ---- packed f32x2 helpers (PTX-only; ptxas never auto-fuses) ----
__device__ __forceinline__ u64 fma2(u64 a, u64 b, u64 c) {
    u64 d; asm("fma.rn.f32x2 %0,%1,%2,%3;" : "=l"(d) : "l"(a), "l"(b), "l"(c)); return d;
}
__device__ __forceinline__ u64 mul2(u64 a, u64 b) {
    u64 d; asm("mul.rn.f32x2 %0,%1,%2;" : "=l"(d) : "l"(a), "l"(b)); return d;
}
__device__ __forceinline__ u64 pack2(float lo, float hi) {
    u64 r; asm("mov.b64 %0,{%1,%2};" : "=l"(r) : "f"(lo), "f"(hi)); return r;
}
__device__ __forceinline__ u64 dup2(float x) { return pack2(x, x); }
__device__ __forceinline__ void unpack2(u64 v, float& lo, float& hi) {
    asm("mov.b64 {%0,%1},%2;" : "=f"(lo), "=f"(hi) : "l"(v));
}

// stable softplus + sigmoid sharing one exp
__device__ __forceinline__ void sp_sig(float z, float& sp, float& sg) {
    float u = __expf(-fabsf(z));
    float d = 1.0f + u;
    float r = __fdividef(1.0f, d);
    sp = fmaxf(z, 0.0f) + __logf(d);
    sg = (z >= 0.0f) ? r : 1.0f - r;
}
__device__ __forceinline__ float sigf(float z) {
    float u = __expf(-fabsf(z));
    float r = __fdividef(1.0f, 1.0f + u);
    return (z >= 0.0f) ? r : 1.0f - r;
}

__global__ void __launch_bounds__(BLK, 1) rnncell_r4_kernel(
    const float* __restrict__ eps, const float* __restrict__ hs,
    const float* __restrict__ W1,  const float* __restrict__ b1,
    const float* __restrict__ W2,  const float* __restrict__ b2,
    const float* __restrict__ W3,  float* __restrict__ out)
{
    __shared__ __align__(16) float sW2 [HH * HH];     // W2[k][j]
    __shared__ __align__(16) float sW2T[HH * HH];     // W2T[j][k]
    __shared__ __align__(16) float sAct[LPC * AST];   // per-lane activation rows

    const int tid = threadIdx.x;
    for (int i = tid; i < HH * HH; i += BLK) {
        float w = W2[i];
        sW2[i] = w;
        sW2T[(i & 31) * HH + (i >> 5)] = w;
    }
    __syncthreads();

    const int quarter = tid & 3;      // 8-unit chunk I own
    const int grp     = tid >> 2;     // group 0..31
    const int co      = quarter * 8;

    // 4 consecutive gids per thread -> vector LDG/STG
    const int gbase = blockIdx.x * LPC + grp * RL;

    // act row for lane (grp,r) = grp*4 + r ; STS banks 16g+8q+.. all distinct,
    // matvec loads are 4-way quarter-broadcast over 8 rows -> conflict-free
    float* act[RL];
    #pragma unroll
    for (int r = 0; r < RL; ++r) act[r] = sAct + (grp * RL + r) * AST;

    // loop-invariant per-chunk weights
    u64 w1ap[4], w1bp[4], b1p[4], b2p[4];
    float w3s[8];
    #pragma unroll
    for (int j = 0; j < 4; ++j) {
        w1ap[j] = pack2(W1[co + 2*j],      W1[co + 2*j + 1]);
        w1bp[j] = pack2(W1[HH + co + 2*j], W1[HH + co + 2*j + 1]);
        b1p [j] = pack2(b1[co + 2*j],      b1[co + 2*j + 1]);
        b2p [j] = pack2(b2[co + 2*j],      b2[co + 2*j + 1]);
    }
    #pragma unroll
    for (int j = 0; j < 8; ++j) w3s[j] = W3[co + j];

    float gam[RL], ec[RL], hc[RL];
    {
        float4 e4 = *(const float4*)(eps + gbase);
        float4 h4 = *(const float4*)(hs  + gbase);
        ec[0]=e4.x; ec[1]=e4.y; ec[2]=e4.z; ec[3]=e4.w;
        hc[0]=h4.x; hc[1]=h4.y; hc[2]=h4.z; hc[3]=h4.w;
        #pragma unroll
        for (int r = 0; r < RL; ++r) gam[r] = 0.0f;
    }

    for (int t = 0; t < TT; ++t) {
        const int tn = (t + 1 < TT) ? t + 1 : t;
        float4 en4 = *(const float4*)(eps + (size_t)tn * BB + gbase);
        float4 hn4 = *(const float4*)(hs  + (size_t)tn * BB + gbase);

        // ---- layer 1 (my 8 units x 4 lanes): z1 -> softplus (staged), sigmoid (regs)
        u64 s1p[RL][4];
        #pragma unroll
        for (int r = 0; r < RL; ++r) {
            const u64 e2 = dup2(ec[r]);
            const u64 g2 = dup2(gam[r]);
            float a1v[8];
            #pragma unroll
            for (int j = 0; j < 4; ++j) {
                u64 z = fma2(e2, w1ap[j], fma2(g2, w1bp[j], b1p[j]));
                float za, zb; unpack2(z, za, zb);
                float spa, sga, spb, sgb;
                sp_sig(za, spa, sga);
                sp_sig(zb, spb, sgb);
                a1v[2*j]   = spa;
                a1v[2*j+1] = spb;
                s1p[r][j]  = pack2(sga, sgb);
            }
            *(float4*)(act[r] + co)     = make_float4(a1v[0], a1v[1], a1v[2], a1v[3]);
            *(float4*)(act[r] + co + 4) = make_float4(a1v[4], a1v[5], a1v[6], a1v[7]);
        }
        __syncwarp();

        // ---- matvec1: z2[my 8 cols] = b2 + sum_k a1[k] * W2[k][.] ----
        u64 acc[RL][4];
        #pragma unroll
        for (int r = 0; r < RL; ++r)
            #pragma unroll
            for (int j = 0; j < 4; ++j) acc[r][j] = b2p[j];

        #pragma unroll
        for (int q = 0; q < 4; ++q) {
            float av[RL][8];
            #pragma unroll
            for (int r = 0; r < RL; ++r) {
                float4 lo = *(const float4*)(act[r] + q * 8);
                float4 hi = *(const float4*)(act[r] + q * 8 + 4);
                av[r][0]=lo.x; av[r][1]=lo.y; av[r][2]=lo.z; av[r][3]=lo.w;
                av[r][4]=hi.x; av[r][5]=hi.y; av[r][6]=hi.z; av[r][7]=hi.w;
            }
            #pragma unroll
            for (int kk = 0; kk < 8; ++kk) {
                const float* wr = sW2 + (q * 8 + kk) * HH + co;
                ulonglong2 wlo = *(const ulonglong2*)wr;
                ulonglong2 whi = *(const ulonglong2*)(wr + 4);
                #pragma unroll
                for (int r = 0; r < RL; ++r) {
                    u64 ak = dup2(av[r][kk]);
                    acc[r][0] = fma2(ak, wlo.x, acc[r][0]);
                    acc[r][1] = fma2(ak, wlo.y, acc[r][1]);
                    acc[r][2] = fma2(ak, whi.x, acc[r][2]);
                    acc[r][3] = fma2(ak, whi.y, acc[r][3]);
                }
            }
        }
        __syncwarp();

        // ---- v2 = sigmoid(z2) * W3, staged ----
        #pragma unroll
        for (int r = 0; r < RL; ++r) {
            float v2v[8];
            #pragma unroll
            for (int j = 0; j < 4; ++j) {
                float za, zb; unpack2(acc[r][j], za, zb);
                v2v[2*j]   = sigf(za) * w3s[2*j];
                v2v[2*j+1] = sigf(zb) * w3s[2*j+1];
            }
            *(float4*)(act[r] + co)     = make_float4(v2v[0], v2v[1], v2v[2], v2v[3]);
            *(float4*)(act[r] + co + 4) = make_float4(v2v[4], v2v[5], v2v[6], v2v[7]);
        }
        __syncwarp();

        // ---- matvec2: t[my 8 rows] = sum_j v2[j] * W2T[j][.] ----
        u64 tacc[RL][4];
        #pragma unroll
        for (int r = 0; r < RL; ++r)
            #pragma unroll
            for (int j = 0; j < 4; ++j) tacc[r][j] = 0ull;

        #pragma unroll
        for (int q = 0; q < 4; ++q) {
            float vv[RL][8];
            #pragma unroll
            for (int r = 0; r < RL; ++r) {
                float4 lo = *(const float4*)(act[r] + q * 8);
                float4 hi = *(const float4*)(act[r] + q * 8 + 4);
                vv[r][0]=lo.x; vv[r][1]=lo.y; vv[r][2]=lo.z; vv[r][3]=lo.w;
                vv[r][4]=hi.x; vv[r][5]=hi.y; vv[r][6]=hi.z; vv[r][7]=hi.w;
            }
            #pragma unroll
            for (int kk = 0; kk < 8; ++kk) {
                const float* wr = sW2T + (q * 8 + kk) * HH + co;
                ulonglong2 wlo = *(const ulonglong2*)wr;
                ulonglong2 whi = *(const ulonglong2*)(wr + 4);
                #pragma unroll
                for (int r = 0; r < RL; ++r) {
                    u64 vk = dup2(vv[r][kk]);
                    tacc[r][0] = fma2(vk, wlo.x, tacc[r][0]);
                    tacc[r][1] = fma2(vk, wlo.y, tacc[r][1]);
                    tacc[r][2] = fma2(vk, whi.x, tacc[r][2]);
                    tacc[r][3] = fma2(vk, whi.y, tacc[r][3]);
                }
            }
        }
        __syncwarp();

        // ---- v1 = sig1 .* t ; partial dots ; 4-thread butterfly ----
        float g0[RL], g1[RL];
        #pragma unroll
        for (int r = 0; r < RL; ++r) {
            u64 g0p = 0ull, g1p = 0ull;
            #pragma unroll
            for (int j = 0; j < 4; ++j) {
                u64 v1 = mul2(s1p[r][j], tacc[r][j]);
                g0p = fma2(v1, w1ap[j], g0p);
                g1p = fma2(v1, w1bp[j], g1p);
            }
            float a, b;
            unpack2(g0p, a, b); g0[r] = a + b;
            unpack2(g1p, a, b); g1[r] = a + b;
        }
        #pragma unroll
        for (int r = 0; r < RL; ++r) {
            g0[r] += __shfl_xor_sync(0xffffffffu, g0[r], 1);
            g0[r] += __shfl_xor_sync(0xffffffffu, g0[r], 2);
            g1[r] += __shfl_xor_sync(0xffffffffu, g1[r], 1);
            g1[r] += __shfl_xor_sync(0xffffffffu, g1[r], 2);
        }

        if (quarter == 0)
            *(float4*)(out + (size_t)t * BB + gbase) =
                make_float4(g0[0], g0[1], g0[2], g0[3]);

        gam[0] = fmaf(hc[0], -g1[0], gam[0]);
        gam[1] = fmaf(hc[1], -g1[1], gam[1]);
        gam[2] = fmaf(hc[2], -g1[2], gam[2]);
        gam[3] = fmaf(hc[3], -g1[3], gam[3]);

        ec[0]=en4.x; ec[1]=en4.y; ec[2]=en4.z; ec[3]=en4.w;
        hc[0]=hn4.x; hc[1]=hn4.y; hc[2]=hn4.z; hc[3]=hn4.w;
    }
}

extern "C" void kernel_launch(void* const* d_in, const int* in_sizes, int n_in,
                              void* d_out, int out_size) {
    const float* eps = (const float*)d_in[0];
    const float* hs  = (const float*)d_in[1];
    const float* W1  = (const float*)d_in[2];
    const float* b1  = (const float*)d_in[3];
    const float* W2  = (const float*)d_in[4];
    const float* b2  = (const float*)d_in[5];
    const float* W3  = (const float*)d_in[6];
    float* out = (float*)d_out;

    // 16384 lanes / 128 per CTA = 128 CTAs x 128 threads (1 CTA/SM, 1 warp/SMSP)
    rnncell_r4_kernel<<<BB / LPC, BLK>>>(eps, hs, W1, b1, W2, b2, W3, out);
}